// round 9
// baseline (speedup 1.0000x reference)
#include <cuda_runtime.h>
#include <cuda_bf16.h>
#include <cstdint>
#include <cstddef>

#define BSZ       64
#define SEQLEN    512
#define NSTEP     255              // sequential LSE steps per direction
#define NT        48
#define NT2       (NT * NT)
#define START_TAG 46
#define END_TAG   47
#define TPB       384              // 48 x 8
#define PD        6                // smem ring stages
#define WAITN     3                // cp.async wait depth (stage k+1 ready at step k)
#define ROWPF     52               // fwd pad: banks (20*sub+j)%32 distinct
#define ROWPB     56               // bwd pad: banks (24*i+sub)%32 distinct; >=48 (no overlap!)
#define STGF      (NT * ROWPB)     // stage stride in floats (56 >= 52)
#define STGB      (STGF * 4)       // stage stride bytes = 10752
#define NF4       (NT2 / 4)        // 576 float4 per tile

// Cross-kernel scratch.
__device__ float g_fw[BSZ][NT + 1];   // [0..47]=v_fwd, [48]=C offset
__device__ float g_bw[BSZ][NT + 1];
__device__ float g_ts[BSZ];
__device__ int   g_is64;

__global__ void crf_prep(const int* __restrict__ tgt32, float* __restrict__ out) {
    int lane = threadIdx.x;
    int v = tgt32[2 * lane + 1];
    int all0 = __all_sync(0xffffffffu, v == 0);
    if (lane == 0) {
        g_is64 = all0;
        out[0] = 0.0f;
    }
}

__device__ __forceinline__ void cpa16(uint32_t dst, const void* src) {
    asm volatile("cp.async.cg.shared.global [%0], [%1], 16;\n" :: "r"(dst), "l"(src));
}
__device__ __forceinline__ void cpa_commit() {
    asm volatile("cp.async.commit_group;\n" ::: "memory");
}
template <int N>
__device__ __forceinline__ void cpa_wait() {
    asm volatile("cp.async.wait_group %0;\n" :: "n"(N) : "memory");
}

// 128 CTAs: blockIdx.x = 2*b + dir. dir=0: forward over tiles 1..255 (+target
// score). dir=1: backward (beta) over tiles 511..256. 48-wide LSE recurrence.
// Normalization: v_k = log(s) - (v_{k-1}[0] + 4), offset accumulated in C
// (true r = v + C). v stays bounded ~[-9,11] so exp args are fp32-safe.
// Tiles stream through a PD-stage padded dynamic-smem ring (coalesced 16B
// cp.async); next step's 6 operands are register-prefetched one step early.
__global__ __launch_bounds__(TPB, 1) void crf_main(
    const float* __restrict__ tr,
    const void*  __restrict__ tgt)
{
    extern __shared__ __align__(16) float dsm[];    // PD stages of STGF floats
    __shared__ float shr[2][NT];
    __shared__ float ts_sh;

    const int tid = threadIdx.x;
    const int b   = blockIdx.x >> 1;
    const int dir = blockIdx.x & 1;
    const int grp = tid >> 3;   // fwd: column j | bwd: row i
    const int sub = tid & 7;

    const float* __restrict__ tb = tr + (size_t)b * SEQLEN * NT2;

    const uint32_t tbase = (uint32_t)__cvta_generic_to_shared(dsm);
    const int f1 = tid;
    const int f2 = tid + TPB;
    const int rowp = dir ? ROWPB : ROWPF;
    const uint32_t d1 = (uint32_t)((f1 / 12) * (rowp * 4) + (f1 % 12) * 16);
    const uint32_t d2 = (uint32_t)((f2 / 12) * (rowp * 4) + (f2 % 12) * 16);

    #define TILE_T(k) (dir ? (SEQLEN - 1 - (k)) : (k))

    if (tid == 0) ts_sh = 0.0f;
    if (tid < NT) {
        shr[0][tid] = dir
            ? tb[(size_t)(SEQLEN - 1) * NT2 + tid * NT + END_TAG]  // beta_510
            : tb[START_TAG * NT + tid];                             // forw_1
    }

    // ---- prologue: stage tiles k = 1 .. PD-1 ----
    #pragma unroll
    for (int k = 1; k < PD; ++k) {
        uint32_t sb = tbase + (uint32_t)k * STGB;
        const char* s = (const char*)(tb + (size_t)TILE_T(k) * NT2);
        cpa16(sb + d1, s + (size_t)f1 * 16);
        if (tid < NF4 - TPB) cpa16(sb + d2, s + (size_t)f2 * 16);
        cpa_commit();
    }

    // ---- target path score (fwd CTA only; overlaps prologue latency) ----
    if (dir == 0) {
        const int is64 = g_is64;
        float ts = 0.0f;
        for (int s = tid; s < SEQLEN; s += TPB) {
            int cur, prv;
            if (is64) {
                const long long* t64 = (const long long*)tgt + (size_t)b * SEQLEN;
                cur = (int)t64[s];
                prv = (s == 0) ? START_TAG : (int)t64[s - 1];
            } else {
                const int* t32 = (const int*)tgt + b * SEQLEN;
                cur = t32[s];
                prv = (s == 0) ? START_TAG : t32[s - 1];
            }
            ts += tb[(size_t)s * NT2 + prv * NT + cur];
        }
        #pragma unroll
        for (int m = 16; m; m >>= 1) ts += __shfl_xor_sync(0xffffffffu, ts, m);
        if ((tid & 31) == 0) atomicAdd(&ts_sh, ts);
    }

    // ---- per-thread smem read offsets (conflict-free) ----
    // fwd: tile[(sub+8k)*52 + j]   banks (20*sub+j)%32 distinct in warp
    // bwd: tile[i*56 + sub + 8k]   banks (24*i+sub)%32 distinct in warp
    const int step8 = dir ? 8 : (8 * ROWPF);
    const int q0 = dir ? (grp * ROWPB + sub) : (sub * ROWPF + grp);
    const int q1 = q0 + step8;
    const int q2 = q0 + 2 * step8;
    const int q3 = q0 + 3 * step8;
    const int q4 = q0 + 4 * step8;
    const int q5 = q0 + 5 * step8;

    // ---- preload step-1 operands into registers ----
    cpa_wait<PD - 2>();   // group for stage 1 retired
    __syncthreads();      // copies visible across threads
    float cur[6];
    {
        const float* sb1 = dsm + 1 * STGF;
        cur[0] = sb1[q0]; cur[1] = sb1[q1]; cur[2] = sb1[q2];
        cur[3] = sb1[q3]; cur[4] = sb1[q4]; cur[5] = sb1[q5];
    }

    float C = 0.0f;

    // ---- recurrence: k = 1 .. 255 ----
    for (int k = 1; k <= NSTEP; ++k) {
        cpa_wait<WAITN>();   // stage k+1 copies complete
        __syncthreads();     // shr[k-1] + stage k+1 visible; old readers done

        // Refill freed stage with tile k+PD-1.
        if (k + PD - 1 <= NSTEP) {
            uint32_t sb = tbase + (uint32_t)((k + PD - 1) % PD) * STGB;
            const char* s = (const char*)(tb + (size_t)TILE_T(k + PD - 1) * NT2);
            cpa16(sb + d1, s + (size_t)f1 * 16);
            if (tid < NF4 - TPB) cpa16(sb + d2, s + (size_t)f2 * 16);
        }
        cpa_commit();

        const float* __restrict__ rin = shr[(k + 1) & 1];
        const float r0 = rin[sub];
        const float r1 = rin[sub +  8];
        const float r2 = rin[sub + 16];
        const float r3 = rin[sub + 24];
        const float r4 = rin[sub + 32];
        const float r5 = rin[sub + 40];

        float e0 = __expf(r0 + cur[0]);
        float e1 = __expf(r1 + cur[1]);
        float e2 = __expf(r2 + cur[2]);
        float e3 = __expf(r3 + cur[3]);
        float e4 = __expf(r4 + cur[4]);
        float e5 = __expf(r5 + cur[5]);

        // Register-prefetch step k+1's operands (stage ready; hides LDS
        // latency under the reduction tail).
        if (k < NSTEP) {
            const float* nb = dsm + ((k + 1) % PD) * STGF;
            cur[0] = nb[q0]; cur[1] = nb[q1]; cur[2] = nb[q2];
            cur[3] = nb[q3]; cur[4] = nb[q4]; cur[5] = nb[q5];
        }

        float s = ((e0 + e1) + (e2 + e3)) + (e4 + e5);
        s += __shfl_xor_sync(0xffffffffu, s, 1);
        s += __shfl_xor_sync(0xffffffffu, s, 2);
        s += __shfl_xor_sync(0xffffffffu, s, 4);
        if (sub == 0) shr[k & 1][grp] = __logf(s) - (r0 + 4.0f);
        if (tid == 0) C += r0 + 4.0f;   // accumulated normalization offset
    }

    __syncthreads();
    float* dst = dir ? g_bw[b] : g_fw[b];
    if (tid < NT) dst[tid] = shr[NSTEP & 1][tid];
    if (tid == 0) {
        dst[NT] = C;
        if (dir == 0) g_ts[b] = ts_sh;
    }
    #undef TILE_T
}

// Combine: r_511[END] = LSE_i(v_f[i] + v_b[i]) + C_f + C_b.
__global__ void crf_combine(float* __restrict__ out) {
    const int b = blockIdx.x;
    const int i = threadIdx.x;
    __shared__ float sv[NT];
    if (i < NT) sv[i] = g_fw[b][i] + g_bw[b][i];
    __syncthreads();
    if (i == 0) {
        float m = sv[0];
        #pragma unroll
        for (int k = 1; k < NT; ++k) m = fmaxf(m, sv[k]);
        float s = 0.0f;
        #pragma unroll
        for (int k = 0; k < NT; ++k) s += __expf(sv[k] - m);
        float F = __logf(s) + m + g_fw[b][NT] + g_bw[b][NT];
        atomicAdd(out, (F - g_ts[b]) * (1.0f / (float)BSZ));
    }
}

extern "C" void kernel_launch(void* const* d_in, const int* in_sizes, int n_in,
                              void* d_out, int out_size) {
    const void* trans = d_in[0];
    const void* tgt   = d_in[1];
    if (n_in >= 2 && in_sizes[0] < in_sizes[1]) {
        trans = d_in[1];
        tgt   = d_in[0];
    }
    const int dyn = PD * STGB;   // 64512 B dynamic smem ring
    cudaFuncSetAttribute(crf_main, cudaFuncAttributeMaxDynamicSharedMemorySize, dyn);
    crf_prep<<<1, 32>>>((const int*)tgt, (float*)d_out);
    crf_main<<<2 * BSZ, TPB, dyn>>>((const float*)trans, tgt);
    crf_combine<<<BSZ, 64>>>((float*)d_out);
}

// round 10
// speedup vs baseline: 1.2038x; 1.2038x over previous
#include <cuda_runtime.h>
#include <cuda_bf16.h>
#include <cstdint>
#include <cstddef>

#define BSZ       64
#define SEQLEN    512
#define NSTEP     255              // sequential LSE steps per direction
#define NT        48
#define NT2       (NT * NT)
#define START_TAG 46
#define END_TAG   47
#define TPB       384              // 48 x 8
#define PD        4                // smem ring stages (power of 2, static)
#define ROWPF     52               // fwd pad: banks (20*sub+j)%32 distinct
#define ROWPB     56               // bwd pad: banks (24*i+sub)%32 distinct; >=48 => no overlap
#define STGF      (NT * 56)        // stage stride floats (max of both layouts)
#define STGB      (STGF * 4)       // 10752 B/stage; 4 stages = 43008 B static
#define NF4       (NT2 / 4)        // 576 float4 per tile

// Cross-kernel scratch.
__device__ float g_fw[BSZ][NT + 1];   // [0..47]=v_fwd, [48]=C offset
__device__ float g_bw[BSZ][NT + 1];
__device__ float g_ts[BSZ];
__device__ int   g_is64;

__global__ void crf_prep(const int* __restrict__ tgt32, float* __restrict__ out) {
    int lane = threadIdx.x;
    int v = tgt32[2 * lane + 1];
    int all0 = __all_sync(0xffffffffu, v == 0);
    if (lane == 0) {
        g_is64 = all0;
        out[0] = 0.0f;
    }
}

__device__ __forceinline__ void cpa16(uint32_t dst, const void* src) {
    asm volatile("cp.async.cg.shared.global [%0], [%1], 16;\n" :: "r"(dst), "l"(src));
}
__device__ __forceinline__ void cpa_commit() {
    asm volatile("cp.async.commit_group;\n" ::: "memory");
}
__device__ __forceinline__ void cpa_wait2() {
    asm volatile("cp.async.wait_group %0;\n" :: "n"(PD - 2) : "memory");
}

// 128 CTAs: blockIdx.x = 2*b + dir. dir=0: forward over tiles 1..255 (+target
// score). dir=1: backward (beta) over tiles 511..256. 48-wide LSE recurrence.
// Normalization: v_k = log(s) - (v_{k-1}[0] + 4); true value = v + C.
// v stays bounded (~[-9,11]) so exp args are fp32-safe without a fresh max.
// Tiles stream through a 4-stage padded static-smem ring via coalesced 16B
// cp.async; padded row strides make the scattered LDS bank-conflict-free.
__global__ __launch_bounds__(TPB, 1) void crf_main(
    const float* __restrict__ tr,
    const void*  __restrict__ tgt)
{
    __shared__ __align__(16) float tile[PD][STGF];
    __shared__ float shr[2][NT];
    __shared__ float ts_sh;

    const int tid = threadIdx.x;
    const int b   = blockIdx.x >> 1;
    const int dir = blockIdx.x & 1;
    const int grp = tid >> 3;   // fwd: column j | bwd: row i
    const int sub = tid & 7;

    const float* __restrict__ tb = tr + (size_t)b * SEQLEN * NT2;

    const uint32_t tbase = (uint32_t)__cvta_generic_to_shared(&tile[0][0]);
    const int f1 = tid;
    const int f2 = tid + TPB;
    const int rowp = dir ? ROWPB : ROWPF;
    const uint32_t d1 = (uint32_t)((f1 / 12) * (rowp * 4) + (f1 % 12) * 16);
    const uint32_t d2 = (uint32_t)((f2 / 12) * (rowp * 4) + (f2 % 12) * 16);

    #define TILE_T(k) (dir ? (SEQLEN - 1 - (k)) : (k))

    if (tid == 0) ts_sh = 0.0f;
    if (tid < NT) {
        shr[0][tid] = dir
            ? tb[(size_t)(SEQLEN - 1) * NT2 + tid * NT + END_TAG]  // beta_510
            : tb[START_TAG * NT + tid];                             // forw_1
    }

    // ---- prologue: stage tiles k = 1 .. PD-1 ----
    #pragma unroll
    for (int k = 1; k < PD; ++k) {
        uint32_t sb = tbase + (uint32_t)k * STGB;
        const char* s = (const char*)(tb + (size_t)TILE_T(k) * NT2);
        cpa16(sb + d1, s + (size_t)f1 * 16);
        if (tid < NF4 - TPB) cpa16(sb + d2, s + (size_t)f2 * 16);
        cpa_commit();
    }

    // ---- target path score (fwd CTA only; overlaps prologue latency) ----
    if (dir == 0) {
        const int is64 = g_is64;
        float ts = 0.0f;
        for (int s = tid; s < SEQLEN; s += TPB) {
            int cur, prv;
            if (is64) {
                const long long* t64 = (const long long*)tgt + (size_t)b * SEQLEN;
                cur = (int)t64[s];
                prv = (s == 0) ? START_TAG : (int)t64[s - 1];
            } else {
                const int* t32 = (const int*)tgt + b * SEQLEN;
                cur = t32[s];
                prv = (s == 0) ? START_TAG : t32[s - 1];
            }
            ts += tb[(size_t)s * NT2 + prv * NT + cur];
        }
        #pragma unroll
        for (int m = 16; m; m >>= 1) ts += __shfl_xor_sync(0xffffffffu, ts, m);
        if ((tid & 31) == 0) atomicAdd(&ts_sh, ts);
    }

    // ---- per-thread smem read offsets (conflict-free) ----
    // fwd: tile[(sub+8k)*52 + j]   banks (20*sub+j)%32 distinct in warp
    // bwd: tile[i*56 + sub + 8k]   banks (24*i+sub)%32 distinct in warp
    const int step8 = dir ? 8 : (8 * ROWPF);
    const int q0 = dir ? (grp * ROWPB + sub) : (sub * ROWPF + grp);
    const int q1 = q0 + step8;
    const int q2 = q0 + 2 * step8;
    const int q3 = q0 + 3 * step8;
    const int q4 = q0 + 4 * step8;
    const int q5 = q0 + 5 * step8;

    float C = 0.0f;

    // ---- recurrence: k = 1 .. 255 ----
    for (int k = 1; k <= NSTEP; ++k) {
        cpa_wait2();         // stage k copies complete (this thread)
        __syncthreads();     // cross-thread visibility; stage k-1 readers done

        // Refill freed stage with tile k+PD-1.
        if (k + PD - 1 <= NSTEP) {
            uint32_t sb = tbase + (uint32_t)((k + PD - 1) & (PD - 1)) * STGB;
            const char* s = (const char*)(tb + (size_t)TILE_T(k + PD - 1) * NT2);
            cpa16(sb + d1, s + (size_t)f1 * 16);
            if (tid < NF4 - TPB) cpa16(sb + d2, s + (size_t)f2 * 16);
        }
        cpa_commit();

        const float* __restrict__ tl  = tile[k & (PD - 1)];
        const float* __restrict__ rin = shr[(k + 1) & 1];
        const float r0 = rin[sub];          // for sub==0 this is v[0]
        const float r1 = rin[sub +  8];
        const float r2 = rin[sub + 16];
        const float r3 = rin[sub + 24];
        const float r4 = rin[sub + 32];
        const float r5 = rin[sub + 40];

        float e0 = __expf(r0 + tl[q0]);
        float e1 = __expf(r1 + tl[q1]);
        float e2 = __expf(r2 + tl[q2]);
        float e3 = __expf(r3 + tl[q3]);
        float e4 = __expf(r4 + tl[q4]);
        float e5 = __expf(r5 + tl[q5]);

        float s = ((e0 + e1) + (e2 + e3)) + (e4 + e5);
        s += __shfl_xor_sync(0xffffffffu, s, 1);
        s += __shfl_xor_sync(0xffffffffu, s, 2);
        s += __shfl_xor_sync(0xffffffffu, s, 4);
        if (sub == 0) shr[k & 1][grp] = __logf(s) - (r0 + 4.0f);
        if (tid == 0) C += r0 + 4.0f;   // accumulated normalization offset
    }

    __syncthreads();
    float* dst = dir ? g_bw[b] : g_fw[b];
    if (tid < NT) dst[tid] = shr[NSTEP & 1][tid];
    if (tid == 0) {
        dst[NT] = C;
        if (dir == 0) g_ts[b] = ts_sh;
    }
    #undef TILE_T
}

// Combine: r_511[END] = LSE_i(v_f[i] + v_b[i]) + C_f + C_b.
__global__ void crf_combine(float* __restrict__ out) {
    const int b = blockIdx.x;
    const int i = threadIdx.x;
    __shared__ float sv[NT];
    if (i < NT) sv[i] = g_fw[b][i] + g_bw[b][i];
    __syncthreads();
    if (i == 0) {
        float m = sv[0];
        #pragma unroll
        for (int k = 1; k < NT; ++k) m = fmaxf(m, sv[k]);
        float s = 0.0f;
        #pragma unroll
        for (int k = 0; k < NT; ++k) s += __expf(sv[k] - m);
        float F = __logf(s) + m + g_fw[b][NT] + g_bw[b][NT];
        atomicAdd(out, (F - g_ts[b]) * (1.0f / (float)BSZ));
    }
}

extern "C" void kernel_launch(void* const* d_in, const int* in_sizes, int n_in,
                              void* d_out, int out_size) {
    const void* trans = d_in[0];
    const void* tgt   = d_in[1];
    if (n_in >= 2 && in_sizes[0] < in_sizes[1]) {
        trans = d_in[1];
        tgt   = d_in[0];
    }
    crf_prep<<<1, 32>>>((const int*)tgt, (float*)d_out);
    crf_main<<<2 * BSZ, TPB>>>((const float*)trans, tgt);
    crf_combine<<<BSZ, 64>>>((float*)d_out);
}